// round 4
// baseline (speedup 1.0000x reference)
#include <cuda_runtime.h>
#include <cuda_bf16.h>
#include <math.h>

// ---------------------------------------------------------------------------
// GAT 3-layer fused pipeline for GB300.
// d_out layout (fp32): out[N*64] | alpha1[E*4] | alpha2[E*4] | alpha3[E*4]
// ---------------------------------------------------------------------------

#define MAX_N 50000
#define MAX_E 1600000

// Scratch (device globals; no allocations allowed)
__device__ float g_feat[(size_t)MAX_N * 256];   // GEMM output (h), max M=256
__device__ float g_skip[(size_t)MAX_N * 128];   // x @ Wskip
__device__ float g_xin [(size_t)MAX_N * 128];   // current layer input
__device__ float g_as  [(size_t)MAX_N * 4];
__device__ float g_ad  [(size_t)MAX_N * 4];
__device__ float g_s   [(size_t)MAX_N * 4];     // softmax denominators
__device__ float g_agg [(size_t)MAX_N * 256];   // message accumulators
__device__ int   g_src [MAX_E];
__device__ int   g_dst [MAX_E];
__device__ int   g_is64;

// ---------------------------------------------------------------------------
// Vector float atomic-add (sm_90+): 4 floats in one L2 reduction op.
// ---------------------------------------------------------------------------
__device__ __forceinline__ void red_add_v4(float* addr, float4 v) {
    asm volatile("red.global.add.v4.f32 [%0], {%1, %2, %3, %4};"
                 :: "l"(addr), "f"(v.x), "f"(v.y), "f"(v.z), "f"(v.w)
                 : "memory");
}

// ---------------------------------------------------------------------------
// Edge-index dtype sniffing + conversion to int32
// ---------------------------------------------------------------------------
__global__ void detect_idx_kernel(const long long* __restrict__ ei, int n_nodes) {
    if (threadIdx.x == 0 && blockIdx.x == 0) {
        int ok = 1;
        for (int i = 0; i < 16; i++) {
            long long v = ei[i];
            if (v < 0 || v >= (long long)n_nodes) { ok = 0; break; }
        }
        g_is64 = ok;
    }
}

__global__ void convert_idx_kernel(const void* __restrict__ ei, int E) {
    int i = blockIdx.x * blockDim.x + threadIdx.x;
    if (i >= E) return;
    if (g_is64) {
        const long long* p = (const long long*)ei;
        g_src[i] = (int)p[i];
        g_dst[i] = (int)p[(size_t)E + i];
    } else {
        const int* p = (const int*)ei;
        g_src[i] = p[i];
        g_dst[i] = p[E + i];
    }
}

// ---------------------------------------------------------------------------
// Tiled fp32 GEMM: C[n,m] = sum_k A[n,k] * B[k,m]
// BM=BN=64, BK=32, 256 threads, 4x4 per thread. K multiple of 32, M of 64.
// ---------------------------------------------------------------------------
__global__ __launch_bounds__(256)
void gemm_kernel(const float* __restrict__ A, const float* __restrict__ B,
                 float* __restrict__ C, int nRows, int K, int M) {
    __shared__ float As[32][68];   // [k][m] (transposed), pad 4 keeps 16B align
    __shared__ float Bs[32][64];   // [k][n]

    int tid = threadIdx.x;
    int tx = tid & 15, ty = tid >> 4;
    int row0 = blockIdx.y * 64, col0 = blockIdx.x * 64;

    float acc[4][4];
#pragma unroll
    for (int i = 0; i < 4; i++)
#pragma unroll
        for (int j = 0; j < 4; j++) acc[i][j] = 0.f;

    for (int k0 = 0; k0 < K; k0 += 32) {
        // A tile: 64 rows x 32 cols, 512 float4 loads over 256 threads
#pragma unroll
        for (int t = 0; t < 2; t++) {
            int f = tid + t * 256;
            int ar = f >> 3;            // 0..63
            int ac = (f & 7) << 2;      // 0,4,...,28
            int grow = row0 + ar;
            float4 v = make_float4(0.f, 0.f, 0.f, 0.f);
            if (grow < nRows)
                v = *(const float4*)(A + (size_t)grow * K + k0 + ac);
            As[ac + 0][ar] = v.x; As[ac + 1][ar] = v.y;
            As[ac + 2][ar] = v.z; As[ac + 3][ar] = v.w;
        }
        // B tile: 32 rows x 64 cols
#pragma unroll
        for (int t = 0; t < 2; t++) {
            int f = tid + t * 256;
            int br = f >> 4;            // 0..31
            int bc = (f & 15) << 2;     // 0..60
            float4 v = *(const float4*)(B + (size_t)(k0 + br) * M + col0 + bc);
            *(float4*)&Bs[br][bc] = v;
        }
        __syncthreads();
#pragma unroll
        for (int k = 0; k < 32; k++) {
            float4 a = *(const float4*)&As[k][ty << 2];
            float4 b = *(const float4*)&Bs[k][tx << 2];
            acc[0][0] += a.x * b.x; acc[0][1] += a.x * b.y; acc[0][2] += a.x * b.z; acc[0][3] += a.x * b.w;
            acc[1][0] += a.y * b.x; acc[1][1] += a.y * b.y; acc[1][2] += a.y * b.z; acc[1][3] += a.y * b.w;
            acc[2][0] += a.z * b.x; acc[2][1] += a.z * b.y; acc[2][2] += a.z * b.z; acc[2][3] += a.z * b.w;
            acc[3][0] += a.w * b.x; acc[3][1] += a.w * b.y; acc[3][2] += a.w * b.z; acc[3][3] += a.w * b.w;
        }
        __syncthreads();
    }
#pragma unroll
    for (int i = 0; i < 4; i++) {
        int row = row0 + (ty << 2) + i;
        if (row < nRows) {
            float4 v = make_float4(acc[i][0], acc[i][1], acc[i][2], acc[i][3]);
            *(float4*)(C + (size_t)row * M + col0 + (tx << 2)) = v;
        }
    }
}

// ---------------------------------------------------------------------------
// as_[n,h] = sum_c h[n,h,c]*a_src[h,c]; ad_ likewise. One warp per (n,h).
// ---------------------------------------------------------------------------
__global__ __launch_bounds__(256)
void attn_coef_kernel(const float* __restrict__ feat,
                      const float* __restrict__ a_src, const float* __restrict__ a_dst,
                      float* __restrict__ as_, float* __restrict__ ad_,
                      int n, int C) {
    int w = (blockIdx.x * blockDim.x + threadIdx.x) >> 5;
    int lane = threadIdx.x & 31;
    if (w >= n * 4) return;
    int node = w >> 2, h = w & 3;
    const float* fp = feat + (size_t)node * 4 * C + h * C;
    float s1 = 0.f, s2 = 0.f;
    for (int c = lane; c < C; c += 32) {
        float v = fp[c];
        s1 += v * a_src[h * C + c];
        s2 += v * a_dst[h * C + c];
    }
#pragma unroll
    for (int o = 16; o; o >>= 1) {
        s1 += __shfl_xor_sync(0xffffffffu, s1, o);
        s2 += __shfl_xor_sync(0xffffffffu, s2, o);
    }
    if (lane == 0) { as_[w] = s1; ad_[w] = s2; }
}

// ---------------------------------------------------------------------------
// Zero softmax sums + aggregation buffer
// ---------------------------------------------------------------------------
__global__ void init_kernel(float* __restrict__ s, float* __restrict__ agg,
                            int nS, int nA) {
    int i = blockIdx.x * blockDim.x + threadIdx.x;
    if (i < nA) agg[i] = 0.f;
    if (i < nS) s[i] = 0.f;
}

// ---------------------------------------------------------------------------
// Pass A: ex = exp(leaky_relu(as[src]+ad[dst])); accumulate denominator.
// (segment_max is dropped — softmax is shift-invariant and |e| is small.)
// ---------------------------------------------------------------------------
__global__ __launch_bounds__(256)
void edge_exp_kernel(const float* __restrict__ as_, const float* __restrict__ ad_,
                     float* __restrict__ exbuf, float* __restrict__ s, int E) {
    int i = blockIdx.x * blockDim.x + threadIdx.x;
    if (i >= E * 4) return;
    int e = i >> 2, h = i & 3;
    int sn = g_src[e], dn = g_dst[e];
    float v = as_[sn * 4 + h] + ad_[dn * 4 + h];
    v = (v > 0.f) ? v : 0.2f * v;
    float ex = __expf(v);
    exbuf[i] = ex;
    atomicAdd(&s[dn * 4 + h], ex);
}

// ---------------------------------------------------------------------------
// Pass B: alpha = ex/(s+eps), write alpha to output, scatter messages.
// One warp per edge; lane handles 4 consecutive features (float4).
// ---------------------------------------------------------------------------
template <int C>
__global__ __launch_bounds__(256)
void edge_agg_kernel(const float* __restrict__ feat,
                     float* __restrict__ alpha,   // in: ex, out: alpha
                     const float* __restrict__ s,
                     float* __restrict__ agg, int E) {
    constexpr int M = 4 * C;
    int w = (int)((blockIdx.x * (unsigned)blockDim.x + threadIdx.x) >> 5);
    int lane = threadIdx.x & 31;
    if (w >= E) return;
    int sn = g_src[w], dn = g_dst[w];

    float al = 0.f;
    if (lane < 4) {
        float ex = alpha[w * 4 + lane];
        al = ex / (s[dn * 4 + lane] + 1e-16f);
        alpha[w * 4 + lane] = al;
    }
    const float4* fsrc = (const float4*)(feat + (size_t)sn * M);
    float4* adst = (float4*)(agg + (size_t)dn * M);
#pragma unroll
    for (int it = 0; it < M / 128; it++) {
        int f4 = it * 32 + lane;            // float4 index within row
        int head = (f4 * 4) / C;            // 0..3
        float a = __shfl_sync(0xffffffffu, al, head);
        float4 v = fsrc[f4];
        v.x *= a; v.y *= a; v.z *= a; v.w *= a;
        red_add_v4((float*)(adst + f4), v);
    }
}

// ---------------------------------------------------------------------------
// Post layer 1/2: y = LN(elu(agg + b)) * w + b_ln  [+ skip + bskip]
// One warp per node (128 features, float4 per lane).
// ---------------------------------------------------------------------------
__global__ __launch_bounds__(256)
void post_ln_kernel(const float* __restrict__ agg, const float* __restrict__ bias,
                    const float* __restrict__ lnw, const float* __restrict__ lnb,
                    const float* __restrict__ skip, const float* __restrict__ bskip,
                    float* __restrict__ xout, int n) {
    int w = (blockIdx.x * blockDim.x + threadIdx.x) >> 5;
    int lane = threadIdx.x & 31;
    if (w >= n) return;
    int f = lane << 2;
    float4 v = *(const float4*)(agg + (size_t)w * 128 + f);
    float4 bb = *(const float4*)(bias + f);
    v.x += bb.x; v.y += bb.y; v.z += bb.z; v.w += bb.w;
    // elu
    v.x = (v.x > 0.f) ? v.x : expm1f(v.x);
    v.y = (v.y > 0.f) ? v.y : expm1f(v.y);
    v.z = (v.z > 0.f) ? v.z : expm1f(v.z);
    v.w = (v.w > 0.f) ? v.w : expm1f(v.w);
    float s1 = v.x + v.y + v.z + v.w;
    float s2 = v.x * v.x + v.y * v.y + v.z * v.z + v.w * v.w;
#pragma unroll
    for (int o = 16; o; o >>= 1) {
        s1 += __shfl_xor_sync(0xffffffffu, s1, o);
        s2 += __shfl_xor_sync(0xffffffffu, s2, o);
    }
    float mu = s1 * (1.f / 128.f);
    float var = s2 * (1.f / 128.f) - mu * mu;
    float inv = rsqrtf(var + 1e-5f);
    float4 wv = *(const float4*)(lnw + f);
    float4 bv = *(const float4*)(lnb + f);
    float4 y;
    y.x = (v.x - mu) * inv * wv.x + bv.x;
    y.y = (v.y - mu) * inv * wv.y + bv.y;
    y.z = (v.z - mu) * inv * wv.z + bv.z;
    y.w = (v.w - mu) * inv * wv.w + bv.w;
    if (skip) {
        float4 sk = *(const float4*)(skip + (size_t)w * 128 + f);
        float4 bs = *(const float4*)(bskip + f);
        y.x += sk.x + bs.x; y.y += sk.y + bs.y;
        y.z += sk.z + bs.z; y.w += sk.w + bs.w;
    }
    *(float4*)(xout + (size_t)w * 128 + f) = y;
}

// ---------------------------------------------------------------------------
// Final: out[n,c] = mean over 4 heads of agg[n,h,c] + b3[c]
// ---------------------------------------------------------------------------
__global__ void finalize_kernel(const float* __restrict__ agg,
                                const float* __restrict__ b3,
                                float* __restrict__ out, int n) {
    int i = blockIdx.x * blockDim.x + threadIdx.x;
    if (i >= n * 64) return;
    int node = i >> 6, c = i & 63;
    const float* p = agg + (size_t)node * 256;
    out[i] = 0.25f * (p[c] + p[64 + c] + p[128 + c] + p[192 + c]) + b3[c];
}

// ---------------------------------------------------------------------------
// Host
// ---------------------------------------------------------------------------
extern "C" void kernel_launch(void* const* d_in, const int* in_sizes, int n_in,
                              void* d_out, int out_size) {
    const float* x      = (const float*)d_in[0];
    const void*  ei     = d_in[1];
    const float* W1     = (const float*)d_in[2];
    const float* a_src1 = (const float*)d_in[3];
    const float* a_dst1 = (const float*)d_in[4];
    const float* b1     = (const float*)d_in[5];
    const float* ln1_w  = (const float*)d_in[6];
    const float* ln1_b  = (const float*)d_in[7];
    const float* Wskip  = (const float*)d_in[8];
    const float* bskip  = (const float*)d_in[9];
    const float* W2     = (const float*)d_in[10];
    const float* a_src2 = (const float*)d_in[11];
    const float* a_dst2 = (const float*)d_in[12];
    const float* b2     = (const float*)d_in[13];
    const float* ln2_w  = (const float*)d_in[14];
    const float* ln2_b  = (const float*)d_in[15];
    const float* W3     = (const float*)d_in[16];
    const float* a_src3 = (const float*)d_in[17];
    const float* a_dst3 = (const float*)d_in[18];
    const float* b3     = (const float*)d_in[19];

    int N = in_sizes[0] / 128;
    int E = in_sizes[1] / 2;

    float* out    = (float*)d_out;
    float* alpha1 = out + (size_t)N * 64;
    float* alpha2 = alpha1 + (size_t)E * 4;
    float* alpha3 = alpha2 + (size_t)E * 4;

    float *feat, *skip, *xin, *as_, *ad_, *s, *agg;
    cudaGetSymbolAddress((void**)&feat, g_feat);
    cudaGetSymbolAddress((void**)&skip, g_skip);
    cudaGetSymbolAddress((void**)&xin,  g_xin);
    cudaGetSymbolAddress((void**)&as_,  g_as);
    cudaGetSymbolAddress((void**)&ad_,  g_ad);
    cudaGetSymbolAddress((void**)&s,    g_s);
    cudaGetSymbolAddress((void**)&agg,  g_agg);

    const int TB = 256;
    dim3 gemm_grid2(2, (N + 63) / 64);   // M=128
    dim3 gemm_grid4(4, (N + 63) / 64);   // M=256
    int attn_blocks  = (N * 4 * 32 + TB - 1) / TB;
    int initS_blocks = (N * 128 + TB - 1) / TB;
    int initL_blocks = (N * 256 + TB - 1) / TB;
    int edgeA_blocks = (E * 4 + TB - 1) / TB;
    int eagg_blocks  = (int)(((long long)E * 32 + TB - 1) / TB);
    int post_blocks  = (N * 32 + TB - 1) / TB;
    int fin_blocks   = (N * 64 + TB - 1) / TB;

    // Edge index decode (int64 vs int32)
    detect_idx_kernel<<<1, 32>>>((const long long*)ei, N);
    convert_idx_kernel<<<(E + TB - 1) / TB, TB>>>(ei, E);

    // ---- Layer 1 ----
    gemm_kernel<<<gemm_grid2, TB>>>(x, W1, feat, N, 128, 128);
    gemm_kernel<<<gemm_grid2, TB>>>(x, Wskip, skip, N, 128, 128);
    attn_coef_kernel<<<attn_blocks, TB>>>(feat, a_src1, a_dst1, as_, ad_, N, 32);
    init_kernel<<<initS_blocks, TB>>>(s, agg, N * 4, N * 128);
    edge_exp_kernel<<<edgeA_blocks, TB>>>(as_, ad_, alpha1, s, E);
    edge_agg_kernel<32><<<eagg_blocks, TB>>>(feat, alpha1, s, agg, E);
    post_ln_kernel<<<post_blocks, TB>>>(agg, b1, ln1_w, ln1_b, skip, bskip, xin, N);

    // ---- Layer 2 ----
    gemm_kernel<<<gemm_grid2, TB>>>(xin, W2, feat, N, 128, 128);
    attn_coef_kernel<<<attn_blocks, TB>>>(feat, a_src2, a_dst2, as_, ad_, N, 32);
    init_kernel<<<initS_blocks, TB>>>(s, agg, N * 4, N * 128);
    edge_exp_kernel<<<edgeA_blocks, TB>>>(as_, ad_, alpha2, s, E);
    edge_agg_kernel<32><<<eagg_blocks, TB>>>(feat, alpha2, s, agg, E);
    post_ln_kernel<<<post_blocks, TB>>>(agg, b2, ln2_w, ln2_b, nullptr, nullptr, xin, N);

    // ---- Layer 3 ----
    gemm_kernel<<<gemm_grid4, TB>>>(xin, W3, feat, N, 128, 256);
    attn_coef_kernel<<<attn_blocks, TB>>>(feat, a_src3, a_dst3, as_, ad_, N, 64);
    init_kernel<<<initL_blocks, TB>>>(s, agg, N * 4, N * 256);
    edge_exp_kernel<<<edgeA_blocks, TB>>>(as_, ad_, alpha3, s, E);
    edge_agg_kernel<64><<<eagg_blocks, TB>>>(feat, alpha3, s, agg, E);
    finalize_kernel<<<fin_blocks, TB>>>(agg, b3, out, N);
}

// round 6
// speedup vs baseline: 1.7460x; 1.7460x over previous
#include <cuda_runtime.h>
#include <cuda_bf16.h>
#include <math.h>

// ---------------------------------------------------------------------------
// GAT 3-layer fused pipeline for GB300 — round 4: dst-CSR, atomic-free edges.
// d_out layout (fp32): out[N*64] | alpha1[E*4] | alpha2[E*4] | alpha3[E*4]
// ---------------------------------------------------------------------------

#define MAX_N 50000
#define MAX_E 1600000

// Scratch (device globals; no allocations allowed)
__device__ float g_feat[(size_t)MAX_N * 256];   // GEMM output (h), max M=256
__device__ float g_skip[(size_t)MAX_N * 128];   // x @ Wskip
__device__ float g_xin [(size_t)MAX_N * 128];   // current layer input
__device__ float g_as  [(size_t)MAX_N * 4];
__device__ float g_ad  [(size_t)MAX_N * 4];
__device__ float g_agg [(size_t)MAX_N * 256];   // per-node aggregated messages
__device__ float g_ex  [(size_t)MAX_E * 4];     // exp(e) in CSR order
__device__ int   g_src [MAX_E];
__device__ int   g_dst [MAX_E];
__device__ int2  g_csr [MAX_E];                 // {src, original edge id}, dst-grouped
__device__ int   g_rowstart[MAX_N + 1];
__device__ int   g_deg   [MAX_N];
__device__ int   g_cursor[MAX_N];
__device__ int   g_is64;

// ---------------------------------------------------------------------------
// Edge-index dtype sniffing + conversion to int32 (+ per-dst degree count)
// ---------------------------------------------------------------------------
__global__ void detect_idx_kernel(const long long* __restrict__ ei, int n_nodes) {
    if (threadIdx.x == 0 && blockIdx.x == 0) {
        int ok = 1;
        for (int i = 0; i < 16; i++) {
            long long v = ei[i];
            if (v < 0 || v >= (long long)n_nodes) { ok = 0; break; }
        }
        g_is64 = ok;
    }
}

__global__ void zero_deg_kernel(int n) {
    int i = blockIdx.x * blockDim.x + threadIdx.x;
    if (i < n) g_deg[i] = 0;
}

__global__ void convert_idx_kernel(const void* __restrict__ ei, int E) {
    int i = blockIdx.x * blockDim.x + threadIdx.x;
    if (i >= E) return;
    int s, d;
    if (g_is64) {
        const long long* p = (const long long*)ei;
        s = (int)p[i];
        d = (int)p[(size_t)E + i];
    } else {
        const int* p = (const int*)ei;
        s = p[i];
        d = p[E + i];
    }
    g_src[i] = s;
    g_dst[i] = d;
    atomicAdd(&g_deg[d], 1);
}

// Single-block exclusive scan of g_deg -> g_rowstart / g_cursor (N <= 1024*chunk)
__global__ __launch_bounds__(1024)
void scan_kernel(int n) {
    __shared__ int ssum[1024];
    int tid = threadIdx.x;
    int chunk = (n + 1023) / 1024;
    int lo = tid * chunk;
    int hi = min(lo + chunk, n);
    int s = 0;
    for (int i = lo; i < hi; i++) s += g_deg[i];
    ssum[tid] = s;
    __syncthreads();
#pragma unroll
    for (int off = 1; off < 1024; off <<= 1) {
        int v = 0;
        if (tid >= off) v = ssum[tid - off];
        __syncthreads();
        if (tid >= off) ssum[tid] += v;
        __syncthreads();
    }
    int run = tid ? ssum[tid - 1] : 0;
    for (int i = lo; i < hi; i++) {
        g_rowstart[i] = run;
        g_cursor[i]   = run;
        run += g_deg[i];
    }
    if (hi == n) g_rowstart[n] = run;
}

__global__ void scatter_kernel(int E) {
    int i = blockIdx.x * blockDim.x + threadIdx.x;
    if (i >= E) return;
    int d = g_dst[i];
    int pos = atomicAdd(&g_cursor[d], 1);
    g_csr[pos] = make_int2(g_src[i], i);
}

// ---------------------------------------------------------------------------
// Tiled fp32 GEMM: C[n,m] = sum_k A[n,k] * B[k,m]
// BM=BN=64, BK=32, 256 threads, 4x4 per thread. K multiple of 32, M of 64.
// ---------------------------------------------------------------------------
__global__ __launch_bounds__(256)
void gemm_kernel(const float* __restrict__ A, const float* __restrict__ B,
                 float* __restrict__ C, int nRows, int K, int M) {
    __shared__ float As[32][68];
    __shared__ float Bs[32][64];

    int tid = threadIdx.x;
    int tx = tid & 15, ty = tid >> 4;
    int row0 = blockIdx.y * 64, col0 = blockIdx.x * 64;

    float acc[4][4];
#pragma unroll
    for (int i = 0; i < 4; i++)
#pragma unroll
        for (int j = 0; j < 4; j++) acc[i][j] = 0.f;

    for (int k0 = 0; k0 < K; k0 += 32) {
#pragma unroll
        for (int t = 0; t < 2; t++) {
            int f = tid + t * 256;
            int ar = f >> 3;
            int ac = (f & 7) << 2;
            int grow = row0 + ar;
            float4 v = make_float4(0.f, 0.f, 0.f, 0.f);
            if (grow < nRows)
                v = *(const float4*)(A + (size_t)grow * K + k0 + ac);
            As[ac + 0][ar] = v.x; As[ac + 1][ar] = v.y;
            As[ac + 2][ar] = v.z; As[ac + 3][ar] = v.w;
        }
#pragma unroll
        for (int t = 0; t < 2; t++) {
            int f = tid + t * 256;
            int br = f >> 4;
            int bc = (f & 15) << 2;
            float4 v = *(const float4*)(B + (size_t)(k0 + br) * M + col0 + bc);
            *(float4*)&Bs[br][bc] = v;
        }
        __syncthreads();
#pragma unroll
        for (int k = 0; k < 32; k++) {
            float4 a = *(const float4*)&As[k][ty << 2];
            float4 b = *(const float4*)&Bs[k][tx << 2];
            acc[0][0] += a.x * b.x; acc[0][1] += a.x * b.y; acc[0][2] += a.x * b.z; acc[0][3] += a.x * b.w;
            acc[1][0] += a.y * b.x; acc[1][1] += a.y * b.y; acc[1][2] += a.y * b.z; acc[1][3] += a.y * b.w;
            acc[2][0] += a.z * b.x; acc[2][1] += a.z * b.y; acc[2][2] += a.z * b.z; acc[2][3] += a.z * b.w;
            acc[3][0] += a.w * b.x; acc[3][1] += a.w * b.y; acc[3][2] += a.w * b.z; acc[3][3] += a.w * b.w;
        }
        __syncthreads();
    }
#pragma unroll
    for (int i = 0; i < 4; i++) {
        int row = row0 + (ty << 2) + i;
        if (row < nRows) {
            float4 v = make_float4(acc[i][0], acc[i][1], acc[i][2], acc[i][3]);
            *(float4*)(C + (size_t)row * M + col0 + (tx << 2)) = v;
        }
    }
}

// ---------------------------------------------------------------------------
// as_[n,h] = sum_c h[n,h,c]*a_src[h,c]; ad_ likewise. One warp per (n,h).
// ---------------------------------------------------------------------------
__global__ __launch_bounds__(256)
void attn_coef_kernel(const float* __restrict__ feat,
                      const float* __restrict__ a_src, const float* __restrict__ a_dst,
                      float* __restrict__ as_, float* __restrict__ ad_,
                      int n, int C) {
    int w = (blockIdx.x * blockDim.x + threadIdx.x) >> 5;
    int lane = threadIdx.x & 31;
    if (w >= n * 4) return;
    int node = w >> 2, h = w & 3;
    const float* fp = feat + (size_t)node * 4 * C + h * C;
    float s1 = 0.f, s2 = 0.f;
    for (int c = lane; c < C; c += 32) {
        float v = fp[c];
        s1 += v * a_src[h * C + c];
        s2 += v * a_dst[h * C + c];
    }
#pragma unroll
    for (int o = 16; o; o >>= 1) {
        s1 += __shfl_xor_sync(0xffffffffu, s1, o);
        s2 += __shfl_xor_sync(0xffffffffu, s2, o);
    }
    if (lane == 0) { as_[w] = s1; ad_[w] = s2; }
}

// ---------------------------------------------------------------------------
// Fused per-destination edge kernel (warp per dst node), atomic-free.
//   Loop A: ex = exp(leakyrelu(as[src]+ad[dst])) -> g_ex (CSR order), denom acc
//   Loop B: alpha[eid] = ex * inv_h   (the required output)
//   Loop C: agg[dst]   = inv_h * sum_e ex_e * feat[src_e]  (registers)
// ---------------------------------------------------------------------------
template <int C>
__global__ __launch_bounds__(256)
void gat_edge_kernel(const float* __restrict__ feat,
                     const float* __restrict__ as_,
                     const float* __restrict__ ad_,
                     float* __restrict__ alpha,
                     float* __restrict__ agg,
                     int n) {
    constexpr int M  = 4 * C;
    constexpr int NR = M / 128;            // float4 slots per lane (1 or 2)
    int w = (blockIdx.x * blockDim.x + threadIdx.x) >> 5;
    int lane = threadIdx.x & 31;
    if (w >= n) return;
    int start = g_rowstart[w];
    int end   = g_rowstart[w + 1];

    float4 adv = *(const float4*)(ad_ + 4 * (size_t)w);

    // ---- Loop A: ex + denominator partials ----
    float d0 = 0.f, d1 = 0.f, d2 = 0.f, d3 = 0.f;
    for (int i = start + lane; i < end; i += 32) {
        int2 se = g_csr[i];
        float4 av = *(const float4*)(as_ + 4 * (size_t)se.x);
        float e0 = av.x + adv.x; e0 = (e0 > 0.f) ? e0 : 0.2f * e0;
        float e1 = av.y + adv.y; e1 = (e1 > 0.f) ? e1 : 0.2f * e1;
        float e2 = av.z + adv.z; e2 = (e2 > 0.f) ? e2 : 0.2f * e2;
        float e3 = av.w + adv.w; e3 = (e3 > 0.f) ? e3 : 0.2f * e3;
        float x0 = __expf(e0), x1 = __expf(e1), x2 = __expf(e2), x3 = __expf(e3);
        *(float4*)(g_ex + (size_t)i * 4) = make_float4(x0, x1, x2, x3);
        d0 += x0; d1 += x1; d2 += x2; d3 += x3;
    }
    __syncwarp();
#pragma unroll
    for (int o = 16; o; o >>= 1) {
        d0 += __shfl_xor_sync(0xffffffffu, d0, o);
        d1 += __shfl_xor_sync(0xffffffffu, d1, o);
        d2 += __shfl_xor_sync(0xffffffffu, d2, o);
        d3 += __shfl_xor_sync(0xffffffffu, d3, o);
    }
    float i0 = 1.f / (d0 + 1e-16f);
    float i1 = 1.f / (d1 + 1e-16f);
    float i2 = 1.f / (d2 + 1e-16f);
    float i3 = 1.f / (d3 + 1e-16f);

    // ---- Loop B: write alpha output (random 16B per edge) ----
    for (int i = start + lane; i < end; i += 32) {
        int eid = g_csr[i].y;
        float4 xv = *(const float4*)(g_ex + (size_t)i * 4);
        xv.x *= i0; xv.y *= i1; xv.z *= i2; xv.w *= i3;
        *(float4*)(alpha + (size_t)eid * 4) = xv;
    }

    // ---- Loop C: register-accumulated aggregation ----
    float4 acc[NR];
#pragma unroll
    for (int r = 0; r < NR; r++) acc[r] = make_float4(0.f, 0.f, 0.f, 0.f);

#pragma unroll 2
    for (int i = start; i < end; i++) {
        int2 se = g_csr[i];                                    // broadcast
        float4 ex = *(const float4*)(g_ex + (size_t)i * 4);    // broadcast
        const float4* fp = (const float4*)(feat + (size_t)se.x * M);
#pragma unroll
        for (int r = 0; r < NR; r++) {
            int f4 = r * 32 + lane;
            int h  = (f4 * 4) / C;
            float wgt = (h < 2) ? (h == 0 ? ex.x : ex.y)
                                : (h == 2 ? ex.z : ex.w);
            float4 v = fp[f4];
            acc[r].x += wgt * v.x; acc[r].y += wgt * v.y;
            acc[r].z += wgt * v.z; acc[r].w += wgt * v.w;
        }
    }

    float4* ap = (float4*)(agg + (size_t)w * M);
#pragma unroll
    for (int r = 0; r < NR; r++) {
        int f4 = r * 32 + lane;
        int h  = (f4 * 4) / C;
        float inv = (h < 2) ? (h == 0 ? i0 : i1)
                            : (h == 2 ? i2 : i3);
        acc[r].x *= inv; acc[r].y *= inv; acc[r].z *= inv; acc[r].w *= inv;
        ap[f4] = acc[r];
    }
}

// ---------------------------------------------------------------------------
// Post layer 1/2: y = LN(elu(agg + b)) * w + b_ln  [+ skip + bskip]
// ---------------------------------------------------------------------------
__global__ __launch_bounds__(256)
void post_ln_kernel(const float* __restrict__ agg, const float* __restrict__ bias,
                    const float* __restrict__ lnw, const float* __restrict__ lnb,
                    const float* __restrict__ skip, const float* __restrict__ bskip,
                    float* __restrict__ xout, int n) {
    int w = (blockIdx.x * blockDim.x + threadIdx.x) >> 5;
    int lane = threadIdx.x & 31;
    if (w >= n) return;
    int f = lane << 2;
    float4 v = *(const float4*)(agg + (size_t)w * 128 + f);
    float4 bb = *(const float4*)(bias + f);
    v.x += bb.x; v.y += bb.y; v.z += bb.z; v.w += bb.w;
    v.x = (v.x > 0.f) ? v.x : expm1f(v.x);
    v.y = (v.y > 0.f) ? v.y : expm1f(v.y);
    v.z = (v.z > 0.f) ? v.z : expm1f(v.z);
    v.w = (v.w > 0.f) ? v.w : expm1f(v.w);
    float s1 = v.x + v.y + v.z + v.w;
    float s2 = v.x * v.x + v.y * v.y + v.z * v.z + v.w * v.w;
#pragma unroll
    for (int o = 16; o; o >>= 1) {
        s1 += __shfl_xor_sync(0xffffffffu, s1, o);
        s2 += __shfl_xor_sync(0xffffffffu, s2, o);
    }
    float mu = s1 * (1.f / 128.f);
    float var = s2 * (1.f / 128.f) - mu * mu;
    float inv = rsqrtf(var + 1e-5f);
    float4 wv = *(const float4*)(lnw + f);
    float4 bv = *(const float4*)(lnb + f);
    float4 y;
    y.x = (v.x - mu) * inv * wv.x + bv.x;
    y.y = (v.y - mu) * inv * wv.y + bv.y;
    y.z = (v.z - mu) * inv * wv.z + bv.z;
    y.w = (v.w - mu) * inv * wv.w + bv.w;
    if (skip) {
        float4 sk = *(const float4*)(skip + (size_t)w * 128 + f);
        float4 bs = *(const float4*)(bskip + f);
        y.x += sk.x + bs.x; y.y += sk.y + bs.y;
        y.z += sk.z + bs.z; y.w += sk.w + bs.w;
    }
    *(float4*)(xout + (size_t)w * 128 + f) = y;
}

// ---------------------------------------------------------------------------
// Final: out[n,c] = mean over 4 heads of agg[n,h,c] + b3[c]
// ---------------------------------------------------------------------------
__global__ void finalize_kernel(const float* __restrict__ agg,
                                const float* __restrict__ b3,
                                float* __restrict__ out, int n) {
    int i = blockIdx.x * blockDim.x + threadIdx.x;
    if (i >= n * 64) return;
    int node = i >> 6, c = i & 63;
    const float* p = agg + (size_t)node * 256;
    out[i] = 0.25f * (p[c] + p[64 + c] + p[128 + c] + p[192 + c]) + b3[c];
}

// ---------------------------------------------------------------------------
// Host
// ---------------------------------------------------------------------------
extern "C" void kernel_launch(void* const* d_in, const int* in_sizes, int n_in,
                              void* d_out, int out_size) {
    const float* x      = (const float*)d_in[0];
    const void*  ei     = d_in[1];
    const float* W1     = (const float*)d_in[2];
    const float* a_src1 = (const float*)d_in[3];
    const float* a_dst1 = (const float*)d_in[4];
    const float* b1     = (const float*)d_in[5];
    const float* ln1_w  = (const float*)d_in[6];
    const float* ln1_b  = (const float*)d_in[7];
    const float* Wskip  = (const float*)d_in[8];
    const float* bskip  = (const float*)d_in[9];
    const float* W2     = (const float*)d_in[10];
    const float* a_src2 = (const float*)d_in[11];
    const float* a_dst2 = (const float*)d_in[12];
    const float* b2     = (const float*)d_in[13];
    const float* ln2_w  = (const float*)d_in[14];
    const float* ln2_b  = (const float*)d_in[15];
    const float* W3     = (const float*)d_in[16];
    const float* a_src3 = (const float*)d_in[17];
    const float* a_dst3 = (const float*)d_in[18];
    const float* b3     = (const float*)d_in[19];

    int N = in_sizes[0] / 128;
    int E = in_sizes[1] / 2;

    float* out    = (float*)d_out;
    float* alpha1 = out + (size_t)N * 64;
    float* alpha2 = alpha1 + (size_t)E * 4;
    float* alpha3 = alpha2 + (size_t)E * 4;

    float *feat, *skip, *xin, *as_, *ad_, *agg;
    cudaGetSymbolAddress((void**)&feat, g_feat);
    cudaGetSymbolAddress((void**)&skip, g_skip);
    cudaGetSymbolAddress((void**)&xin,  g_xin);
    cudaGetSymbolAddress((void**)&as_,  g_as);
    cudaGetSymbolAddress((void**)&ad_,  g_ad);
    cudaGetSymbolAddress((void**)&agg,  g_agg);

    const int TB = 256;
    dim3 gemm_grid2(2, (N + 63) / 64);   // M=128
    dim3 gemm_grid4(4, (N + 63) / 64);   // M=256
    int attn_blocks = (N * 4 * 32 + TB - 1) / TB;
    int edgeE_blocks = (E + TB - 1) / TB;
    int node_warp_blocks = (N * 32 + TB - 1) / TB;
    int fin_blocks = (N * 64 + TB - 1) / TB;
    int zero_blocks = (N + TB - 1) / TB;

    // ---- CSR build (once; shared by all 3 layers) ----
    detect_idx_kernel<<<1, 32>>>((const long long*)ei, N);
    zero_deg_kernel<<<zero_blocks, TB>>>(N);
    convert_idx_kernel<<<edgeE_blocks, TB>>>(ei, E);
    scan_kernel<<<1, 1024>>>(N);
    scatter_kernel<<<edgeE_blocks, TB>>>(E);

    // ---- Layer 1 ----
    gemm_kernel<<<gemm_grid2, TB>>>(x, W1, feat, N, 128, 128);
    gemm_kernel<<<gemm_grid2, TB>>>(x, Wskip, skip, N, 128, 128);
    attn_coef_kernel<<<attn_blocks, TB>>>(feat, a_src1, a_dst1, as_, ad_, N, 32);
    gat_edge_kernel<32><<<node_warp_blocks, TB>>>(feat, as_, ad_, alpha1, agg, N);
    post_ln_kernel<<<node_warp_blocks, TB>>>(agg, b1, ln1_w, ln1_b, skip, bskip, xin, N);

    // ---- Layer 2 ----
    gemm_kernel<<<gemm_grid2, TB>>>(xin, W2, feat, N, 128, 128);
    attn_coef_kernel<<<attn_blocks, TB>>>(feat, a_src2, a_dst2, as_, ad_, N, 32);
    gat_edge_kernel<32><<<node_warp_blocks, TB>>>(feat, as_, ad_, alpha2, agg, N);
    post_ln_kernel<<<node_warp_blocks, TB>>>(agg, b2, ln2_w, ln2_b, nullptr, nullptr, xin, N);

    // ---- Layer 3 ----
    gemm_kernel<<<gemm_grid4, TB>>>(xin, W3, feat, N, 128, 256);
    attn_coef_kernel<<<attn_blocks, TB>>>(feat, a_src3, a_dst3, as_, ad_, N, 64);
    gat_edge_kernel<64><<<node_warp_blocks, TB>>>(feat, as_, ad_, alpha3, agg, N);
    finalize_kernel<<<fin_blocks, TB>>>(agg, b3, out, N);
}

// round 8
// speedup vs baseline: 1.9319x; 1.1065x over previous
#include <cuda_runtime.h>
#include <cuda_bf16.h>
#include <math.h>

// ---------------------------------------------------------------------------
// GAT 3-layer fused pipeline for GB300 — round 6: parallel scan + 8x8 GEMM.
// d_out layout (fp32): out[N*64] | alpha1[E*4] | alpha2[E*4] | alpha3[E*4]
// ---------------------------------------------------------------------------

#define MAX_N 50000
#define MAX_E 1600000

__device__ float g_feat[(size_t)MAX_N * 256];
__device__ float g_skip[(size_t)MAX_N * 128];
__device__ float g_xin [(size_t)MAX_N * 128];
__device__ float g_as  [(size_t)MAX_N * 4];
__device__ float g_ad  [(size_t)MAX_N * 4];
__device__ float g_agg [(size_t)MAX_N * 256];
__device__ float g_ex  [(size_t)MAX_E * 4];
__device__ int   g_src [MAX_E];
__device__ int   g_dst [MAX_E];
__device__ int2  g_csr [MAX_E];
__device__ int   g_rowstart[MAX_N + 1];
__device__ int   g_deg   [MAX_N];
__device__ int   g_cursor[MAX_N];
__device__ int   g_scan  [MAX_N];
__device__ int   g_bsum  [64];
__device__ int   g_is64;

// ---------------------------------------------------------------------------
// Edge-index dtype sniffing + conversion to int32 (+ per-dst degree count)
// ---------------------------------------------------------------------------
__global__ void detect_idx_kernel(const long long* __restrict__ ei, int n_nodes) {
    if (threadIdx.x == 0 && blockIdx.x == 0) {
        int ok = 1;
        for (int i = 0; i < 16; i++) {
            long long v = ei[i];
            if (v < 0 || v >= (long long)n_nodes) { ok = 0; break; }
        }
        g_is64 = ok;
    }
}

__global__ void zero_deg_kernel(int n) {
    int i = blockIdx.x * blockDim.x + threadIdx.x;
    if (i < n) g_deg[i] = 0;
}

__global__ void convert_idx_kernel(const void* __restrict__ ei, int E) {
    int i = blockIdx.x * blockDim.x + threadIdx.x;
    if (i >= E) return;
    int s, d;
    if (g_is64) {
        const long long* p = (const long long*)ei;
        s = (int)p[i];
        d = (int)p[(size_t)E + i];
    } else {
        const int* p = (const int*)ei;
        s = p[i];
        d = p[E + i];
    }
    g_src[i] = s;
    g_dst[i] = d;
    atomicAdd(&g_deg[d], 1);
}

// ---------------------------------------------------------------------------
// Parallel 3-phase exclusive scan of g_deg -> g_rowstart / g_cursor
// ---------------------------------------------------------------------------
__global__ __launch_bounds__(1024)
void scan1_kernel(int n) {
    int i = blockIdx.x * 1024 + threadIdx.x;
    int lane = threadIdx.x & 31, wid = threadIdx.x >> 5;
    int v = (i < n) ? g_deg[i] : 0;
    int x = v;
#pragma unroll
    for (int o = 1; o < 32; o <<= 1) {
        int t = __shfl_up_sync(0xffffffffu, x, o);
        if (lane >= o) x += t;
    }
    __shared__ int ws[32];
    if (lane == 31) ws[wid] = x;
    __syncthreads();
    if (wid == 0) {
        int y = ws[lane];
#pragma unroll
        for (int o = 1; o < 32; o <<= 1) {
            int t = __shfl_up_sync(0xffffffffu, y, o);
            if (lane >= o) y += t;
        }
        ws[lane] = y;
    }
    __syncthreads();
    int incl = x + (wid ? ws[wid - 1] : 0);
    if (i < n) g_scan[i] = incl;
    if (threadIdx.x == 1023) g_bsum[blockIdx.x] = incl;
}

__global__ void scan2_kernel(int nb) {   // <<<1, 64>>>; nb <= 64
    int tid = threadIdx.x;
    int lane = tid & 31, wid = tid >> 5;
    int v = (tid < nb) ? g_bsum[tid] : 0;
    int x = v;
#pragma unroll
    for (int o = 1; o < 32; o <<= 1) {
        int t = __shfl_up_sync(0xffffffffu, x, o);
        if (lane >= o) x += t;
    }
    __shared__ int w0;
    if (wid == 0 && lane == 31) w0 = x;
    __syncthreads();
    if (wid == 1) x += w0;
    if (tid < nb) g_bsum[tid] = x;       // inclusive block sums
}

__global__ void scan3_kernel(int n, int nb) {
    int i = blockIdx.x * blockDim.x + threadIdx.x;
    if (i > n) return;
    if (i == n) {
        g_rowstart[n] = g_bsum[nb - 1];
        return;
    }
    int blk = i >> 10;
    int excl = g_scan[i] - g_deg[i] + (blk ? g_bsum[blk - 1] : 0);
    g_rowstart[i] = excl;
    g_cursor[i]   = excl;
}

__global__ void scatter_kernel(int E) {
    int i = blockIdx.x * blockDim.x + threadIdx.x;
    if (i >= E) return;
    int d = g_dst[i];
    int pos = atomicAdd(&g_cursor[d], 1);
    g_csr[pos] = make_int2(g_src[i], i);
}

// ---------------------------------------------------------------------------
// Tiled fp32 GEMM: C[n,m] = sum_k A[n,k] * B[k,m]
// BM=128, BN=128, BK=16, 256 threads, 8x8 per thread (4+4 split tiles).
// K multiple of 16, M multiple of 128.
// ---------------------------------------------------------------------------
__global__ __launch_bounds__(256)
void gemm_kernel(const float* __restrict__ A, const float* __restrict__ B,
                 float* __restrict__ C, int nRows, int K, int M) {
    __shared__ float As[16][136];   // [k][row]; pad 136 -> conflict-free stores
    __shared__ float Bs[16][128];   // [k][col]

    int tid = threadIdx.x;
    int tx = tid & 15, ty = tid >> 4;
    int row0 = blockIdx.y * 128, col0 = blockIdx.x * 128;

    float acc[8][8];
#pragma unroll
    for (int i = 0; i < 8; i++)
#pragma unroll
        for (int j = 0; j < 8; j++) acc[i][j] = 0.f;

    for (int k0 = 0; k0 < K; k0 += 16) {
        // A tile: 128 rows x 16 cols = 512 float4 over 256 threads
#pragma unroll
        for (int t = 0; t < 2; t++) {
            int f = tid + t * 256;
            int ar = f >> 2;            // 0..127
            int ac = (f & 3) << 2;      // 0,4,8,12
            int grow = row0 + ar;
            float4 v = make_float4(0.f, 0.f, 0.f, 0.f);
            if (grow < nRows)
                v = *(const float4*)(A + (size_t)grow * K + k0 + ac);
            As[ac + 0][ar] = v.x; As[ac + 1][ar] = v.y;
            As[ac + 2][ar] = v.z; As[ac + 3][ar] = v.w;
        }
        // B tile: 16 rows x 128 cols = 512 float4
#pragma unroll
        for (int t = 0; t < 2; t++) {
            int f = tid + t * 256;
            int br = f >> 5;            // 0..15
            int bc = (f & 31) << 2;     // 0..124
            *(float4*)&Bs[br][bc] =
                *(const float4*)(B + (size_t)(k0 + br) * M + col0 + bc);
        }
        __syncthreads();
#pragma unroll
        for (int k = 0; k < 16; k++) {
            float4 a0 = *(const float4*)&As[k][ty << 2];
            float4 a1 = *(const float4*)&As[k][64 + (ty << 2)];
            float4 b0 = *(const float4*)&Bs[k][tx << 2];
            float4 b1 = *(const float4*)&Bs[k][64 + (tx << 2)];
            float a[8] = {a0.x, a0.y, a0.z, a0.w, a1.x, a1.y, a1.z, a1.w};
            float b[8] = {b0.x, b0.y, b0.z, b0.w, b1.x, b1.y, b1.z, b1.w};
#pragma unroll
            for (int i = 0; i < 8; i++)
#pragma unroll
                for (int j = 0; j < 8; j++)
                    acc[i][j] += a[i] * b[j];
        }
        __syncthreads();
    }
#pragma unroll
    for (int i = 0; i < 8; i++) {
        int row = row0 + ((i < 4) ? ((ty << 2) + i) : (64 + (ty << 2) + i - 4));
        if (row >= nRows) continue;
        float* cp = C + (size_t)row * M + col0;
        *(float4*)(cp + (tx << 2)) =
            make_float4(acc[i][0], acc[i][1], acc[i][2], acc[i][3]);
        *(float4*)(cp + 64 + (tx << 2)) =
            make_float4(acc[i][4], acc[i][5], acc[i][6], acc[i][7]);
    }
}

// ---------------------------------------------------------------------------
// as_[n,h] = sum_c h[n,h,c]*a_src[h,c]; ad_ likewise. One warp per (n,h).
// ---------------------------------------------------------------------------
__global__ __launch_bounds__(256)
void attn_coef_kernel(const float* __restrict__ feat,
                      const float* __restrict__ a_src, const float* __restrict__ a_dst,
                      float* __restrict__ as_, float* __restrict__ ad_,
                      int n, int C) {
    int w = (blockIdx.x * blockDim.x + threadIdx.x) >> 5;
    int lane = threadIdx.x & 31;
    if (w >= n * 4) return;
    int node = w >> 2, h = w & 3;
    const float* fp = feat + (size_t)node * 4 * C + h * C;
    float s1 = 0.f, s2 = 0.f;
    for (int c = lane; c < C; c += 32) {
        float v = fp[c];
        s1 += v * a_src[h * C + c];
        s2 += v * a_dst[h * C + c];
    }
#pragma unroll
    for (int o = 16; o; o >>= 1) {
        s1 += __shfl_xor_sync(0xffffffffu, s1, o);
        s2 += __shfl_xor_sync(0xffffffffu, s2, o);
    }
    if (lane == 0) { as_[w] = s1; ad_[w] = s2; }
}

// ---------------------------------------------------------------------------
// Fused per-destination edge kernel (warp per dst node), atomic-free.
// ---------------------------------------------------------------------------
template <int C>
__global__ __launch_bounds__(256)
void gat_edge_kernel(const float* __restrict__ feat,
                     const float* __restrict__ as_,
                     const float* __restrict__ ad_,
                     float* __restrict__ alpha,
                     float* __restrict__ agg,
                     int n) {
    constexpr int M  = 4 * C;
    constexpr int NR = M / 128;
    int w = (blockIdx.x * blockDim.x + threadIdx.x) >> 5;
    int lane = threadIdx.x & 31;
    if (w >= n) return;
    int start = g_rowstart[w];
    int end   = g_rowstart[w + 1];

    float4 adv = *(const float4*)(ad_ + 4 * (size_t)w);

    // ---- Loop A: ex + denominator partials ----
    float d0 = 0.f, d1 = 0.f, d2 = 0.f, d3 = 0.f;
    for (int i = start + lane; i < end; i += 32) {
        int2 se = g_csr[i];
        float4 av = *(const float4*)(as_ + 4 * (size_t)se.x);
        float e0 = av.x + adv.x; e0 = (e0 > 0.f) ? e0 : 0.2f * e0;
        float e1 = av.y + adv.y; e1 = (e1 > 0.f) ? e1 : 0.2f * e1;
        float e2 = av.z + adv.z; e2 = (e2 > 0.f) ? e2 : 0.2f * e2;
        float e3 = av.w + adv.w; e3 = (e3 > 0.f) ? e3 : 0.2f * e3;
        float x0 = __expf(e0), x1 = __expf(e1), x2 = __expf(e2), x3 = __expf(e3);
        *(float4*)(g_ex + (size_t)i * 4) = make_float4(x0, x1, x2, x3);
        d0 += x0; d1 += x1; d2 += x2; d3 += x3;
    }
    __syncwarp();
#pragma unroll
    for (int o = 16; o; o >>= 1) {
        d0 += __shfl_xor_sync(0xffffffffu, d0, o);
        d1 += __shfl_xor_sync(0xffffffffu, d1, o);
        d2 += __shfl_xor_sync(0xffffffffu, d2, o);
        d3 += __shfl_xor_sync(0xffffffffu, d3, o);
    }
    float i0 = 1.f / (d0 + 1e-16f);
    float i1 = 1.f / (d1 + 1e-16f);
    float i2 = 1.f / (d2 + 1e-16f);
    float i3 = 1.f / (d3 + 1e-16f);

    // ---- Loop B: write alpha output ----
    for (int i = start + lane; i < end; i += 32) {
        int eid = g_csr[i].y;
        float4 xv = *(const float4*)(g_ex + (size_t)i * 4);
        xv.x *= i0; xv.y *= i1; xv.z *= i2; xv.w *= i3;
        *(float4*)(alpha + (size_t)eid * 4) = xv;
    }

    // ---- Loop C: register-accumulated aggregation ----
    float4 acc[NR];
#pragma unroll
    for (int r = 0; r < NR; r++) acc[r] = make_float4(0.f, 0.f, 0.f, 0.f);

#pragma unroll 2
    for (int i = start; i < end; i++) {
        int2 se = g_csr[i];
        float4 ex = *(const float4*)(g_ex + (size_t)i * 4);
        const float4* fp = (const float4*)(feat + (size_t)se.x * M);
#pragma unroll
        for (int r = 0; r < NR; r++) {
            int f4 = r * 32 + lane;
            int h  = (f4 * 4) / C;
            float wgt = (h < 2) ? (h == 0 ? ex.x : ex.y)
                                : (h == 2 ? ex.z : ex.w);
            float4 v = fp[f4];
            acc[r].x += wgt * v.x; acc[r].y += wgt * v.y;
            acc[r].z += wgt * v.z; acc[r].w += wgt * v.w;
        }
    }

    float4* ap = (float4*)(agg + (size_t)w * M);
#pragma unroll
    for (int r = 0; r < NR; r++) {
        int f4 = r * 32 + lane;
        int h  = (f4 * 4) / C;
        float inv = (h < 2) ? (h == 0 ? i0 : i1)
                            : (h == 2 ? i2 : i3);
        acc[r].x *= inv; acc[r].y *= inv; acc[r].z *= inv; acc[r].w *= inv;
        ap[f4] = acc[r];
    }
}

// ---------------------------------------------------------------------------
// Post layer 1/2: y = LN(elu(agg + b)) * w + b_ln  [+ skip + bskip]
// ---------------------------------------------------------------------------
__global__ __launch_bounds__(256)
void post_ln_kernel(const float* __restrict__ agg, const float* __restrict__ bias,
                    const float* __restrict__ lnw, const float* __restrict__ lnb,
                    const float* __restrict__ skip, const float* __restrict__ bskip,
                    float* __restrict__ xout, int n) {
    int w = (blockIdx.x * blockDim.x + threadIdx.x) >> 5;
    int lane = threadIdx.x & 31;
    if (w >= n) return;
    int f = lane << 2;
    float4 v = *(const float4*)(agg + (size_t)w * 128 + f);
    float4 bb = *(const float4*)(bias + f);
    v.x += bb.x; v.y += bb.y; v.z += bb.z; v.w += bb.w;
    v.x = (v.x > 0.f) ? v.x : expm1f(v.x);
    v.y = (v.y > 0.f) ? v.y : expm1f(v.y);
    v.z = (v.z > 0.f) ? v.z : expm1f(v.z);
    v.w = (v.w > 0.f) ? v.w : expm1f(v.w);
    float s1 = v.x + v.y + v.z + v.w;
    float s2 = v.x * v.x + v.y * v.y + v.z * v.z + v.w * v.w;
#pragma unroll
    for (int o = 16; o; o >>= 1) {
        s1 += __shfl_xor_sync(0xffffffffu, s1, o);
        s2 += __shfl_xor_sync(0xffffffffu, s2, o);
    }
    float mu = s1 * (1.f / 128.f);
    float var = s2 * (1.f / 128.f) - mu * mu;
    float inv = rsqrtf(var + 1e-5f);
    float4 wv = *(const float4*)(lnw + f);
    float4 bv = *(const float4*)(lnb + f);
    float4 y;
    y.x = (v.x - mu) * inv * wv.x + bv.x;
    y.y = (v.y - mu) * inv * wv.y + bv.y;
    y.z = (v.z - mu) * inv * wv.z + bv.z;
    y.w = (v.w - mu) * inv * wv.w + bv.w;
    if (skip) {
        float4 sk = *(const float4*)(skip + (size_t)w * 128 + f);
        float4 bs = *(const float4*)(bskip + f);
        y.x += sk.x + bs.x; y.y += sk.y + bs.y;
        y.z += sk.z + bs.z; y.w += sk.w + bs.w;
    }
    *(float4*)(xout + (size_t)w * 128 + f) = y;
}

// ---------------------------------------------------------------------------
// Final: out[n,c] = mean over 4 heads of agg[n,h,c] + b3[c]
// ---------------------------------------------------------------------------
__global__ void finalize_kernel(const float* __restrict__ agg,
                                const float* __restrict__ b3,
                                float* __restrict__ out, int n) {
    int i = blockIdx.x * blockDim.x + threadIdx.x;
    if (i >= n * 64) return;
    int node = i >> 6, c = i & 63;
    const float* p = agg + (size_t)node * 256;
    out[i] = 0.25f * (p[c] + p[64 + c] + p[128 + c] + p[192 + c]) + b3[c];
}

// ---------------------------------------------------------------------------
// Host
// ---------------------------------------------------------------------------
extern "C" void kernel_launch(void* const* d_in, const int* in_sizes, int n_in,
                              void* d_out, int out_size) {
    const float* x      = (const float*)d_in[0];
    const void*  ei     = d_in[1];
    const float* W1     = (const float*)d_in[2];
    const float* a_src1 = (const float*)d_in[3];
    const float* a_dst1 = (const float*)d_in[4];
    const float* b1     = (const float*)d_in[5];
    const float* ln1_w  = (const float*)d_in[6];
    const float* ln1_b  = (const float*)d_in[7];
    const float* Wskip  = (const float*)d_in[8];
    const float* bskip  = (const float*)d_in[9];
    const float* W2     = (const float*)d_in[10];
    const float* a_src2 = (const float*)d_in[11];
    const float* a_dst2 = (const float*)d_in[12];
    const float* b2     = (const float*)d_in[13];
    const float* ln2_w  = (const float*)d_in[14];
    const float* ln2_b  = (const float*)d_in[15];
    const float* W3     = (const float*)d_in[16];
    const float* a_src3 = (const float*)d_in[17];
    const float* a_dst3 = (const float*)d_in[18];
    const float* b3     = (const float*)d_in[19];

    int N = in_sizes[0] / 128;
    int E = in_sizes[1] / 2;

    float* out    = (float*)d_out;
    float* alpha1 = out + (size_t)N * 64;
    float* alpha2 = alpha1 + (size_t)E * 4;
    float* alpha3 = alpha2 + (size_t)E * 4;

    float *feat, *skip, *xin, *as_, *ad_, *agg;
    cudaGetSymbolAddress((void**)&feat, g_feat);
    cudaGetSymbolAddress((void**)&skip, g_skip);
    cudaGetSymbolAddress((void**)&xin,  g_xin);
    cudaGetSymbolAddress((void**)&as_,  g_as);
    cudaGetSymbolAddress((void**)&ad_,  g_ad);
    cudaGetSymbolAddress((void**)&agg,  g_agg);

    const int TB = 256;
    dim3 gemm_grid1(1, (N + 127) / 128);   // M=128
    dim3 gemm_grid2(2, (N + 127) / 128);   // M=256
    int attn_blocks = (N * 4 * 32 + TB - 1) / TB;
    int edgeE_blocks = (E + TB - 1) / TB;
    int node_warp_blocks = (N * 32 + TB - 1) / TB;
    int fin_blocks = (N * 64 + TB - 1) / TB;
    int zero_blocks = (N + TB - 1) / TB;
    int nb = (N + 1023) / 1024;

    // ---- CSR build (once; shared by all 3 layers) ----
    detect_idx_kernel<<<1, 32>>>((const long long*)ei, N);
    zero_deg_kernel<<<zero_blocks, TB>>>(N);
    convert_idx_kernel<<<edgeE_blocks, TB>>>(ei, E);
    scan1_kernel<<<nb, 1024>>>(N);
    scan2_kernel<<<1, 64>>>(nb);
    scan3_kernel<<<(N + 1 + TB - 1) / TB, TB>>>(N, nb);
    scatter_kernel<<<edgeE_blocks, TB>>>(E);

    // ---- Layer 1 ----
    gemm_kernel<<<gemm_grid1, TB>>>(x, W1, feat, N, 128, 128);
    gemm_kernel<<<gemm_grid1, TB>>>(x, Wskip, skip, N, 128, 128);
    attn_coef_kernel<<<attn_blocks, TB>>>(feat, a_src1, a_dst1, as_, ad_, N, 32);
    gat_edge_kernel<32><<<node_warp_blocks, TB>>>(feat, as_, ad_, alpha1, agg, N);
    post_ln_kernel<<<node_warp_blocks, TB>>>(agg, b1, ln1_w, ln1_b, skip, bskip, xin, N);

    // ---- Layer 2 ----
    gemm_kernel<<<gemm_grid1, TB>>>(xin, W2, feat, N, 128, 128);
    attn_coef_kernel<<<attn_blocks, TB>>>(feat, a_src2, a_dst2, as_, ad_, N, 32);
    gat_edge_kernel<32><<<node_warp_blocks, TB>>>(feat, as_, ad_, alpha2, agg, N);
    post_ln_kernel<<<node_warp_blocks, TB>>>(agg, b2, ln2_w, ln2_b, nullptr, nullptr, xin, N);

    // ---- Layer 3 ----
    gemm_kernel<<<gemm_grid2, TB>>>(xin, W3, feat, N, 128, 256);
    attn_coef_kernel<<<attn_blocks, TB>>>(feat, a_src3, a_dst3, as_, ad_, N, 64);
    gat_edge_kernel<64><<<node_warp_blocks, TB>>>(feat, as_, ad_, alpha3, agg, N);
    finalize_kernel<<<fin_blocks, TB>>>(agg, b3, out, N);
}

// round 9
// speedup vs baseline: 1.9656x; 1.0174x over previous
#include <cuda_runtime.h>
#include <cuda_bf16.h>
#include <math.h>

// ---------------------------------------------------------------------------
// GAT 3-layer fused pipeline for GB300 — round 8:
//   * post_ln / finalize fused into gat_edge register epilogue
//   * coalesced alpha kernel (no random scatter), CSR payload int2 -> int
// d_out layout (fp32): out[N*64] | alpha1[E*4] | alpha2[E*4] | alpha3[E*4]
// ---------------------------------------------------------------------------

#define MAX_N 50000
#define MAX_E 1600000

__device__ float g_feat[(size_t)MAX_N * 256];
__device__ float g_skip[(size_t)MAX_N * 128];
__device__ float g_xin [(size_t)MAX_N * 128];
__device__ float g_as  [(size_t)MAX_N * 4];
__device__ float g_ad  [(size_t)MAX_N * 4];
__device__ float g_inv [(size_t)MAX_N * 4];     // per-(dst,head) 1/denominator
__device__ float g_ex  [(size_t)MAX_E * 4];     // exp(e) in CSR order
__device__ int   g_src [MAX_E];
__device__ int   g_dst [MAX_E];
__device__ int   g_csr [MAX_E];                 // src only, dst-grouped
__device__ int   g_rowstart[MAX_N + 1];
__device__ int   g_deg   [MAX_N];
__device__ int   g_cursor[MAX_N];
__device__ int   g_scan  [MAX_N];
__device__ int   g_bsum  [64];
__device__ int   g_is64;

// ---------------------------------------------------------------------------
// Edge-index dtype sniffing + conversion to int32 (+ per-dst degree count)
// ---------------------------------------------------------------------------
__global__ void detect_idx_kernel(const long long* __restrict__ ei, int n_nodes) {
    if (threadIdx.x == 0 && blockIdx.x == 0) {
        int ok = 1;
        for (int i = 0; i < 16; i++) {
            long long v = ei[i];
            if (v < 0 || v >= (long long)n_nodes) { ok = 0; break; }
        }
        g_is64 = ok;
    }
}

__global__ void zero_deg_kernel(int n) {
    int i = blockIdx.x * blockDim.x + threadIdx.x;
    if (i < n) g_deg[i] = 0;
}

__global__ void convert_idx_kernel(const void* __restrict__ ei, int E) {
    int i = blockIdx.x * blockDim.x + threadIdx.x;
    if (i >= E) return;
    int s, d;
    if (g_is64) {
        const long long* p = (const long long*)ei;
        s = (int)p[i];
        d = (int)p[(size_t)E + i];
    } else {
        const int* p = (const int*)ei;
        s = p[i];
        d = p[E + i];
    }
    g_src[i] = s;
    g_dst[i] = d;
    atomicAdd(&g_deg[d], 1);
}

// ---------------------------------------------------------------------------
// Parallel 3-phase exclusive scan of g_deg -> g_rowstart / g_cursor
// ---------------------------------------------------------------------------
__global__ __launch_bounds__(1024)
void scan1_kernel(int n) {
    int i = blockIdx.x * 1024 + threadIdx.x;
    int lane = threadIdx.x & 31, wid = threadIdx.x >> 5;
    int v = (i < n) ? g_deg[i] : 0;
    int x = v;
#pragma unroll
    for (int o = 1; o < 32; o <<= 1) {
        int t = __shfl_up_sync(0xffffffffu, x, o);
        if (lane >= o) x += t;
    }
    __shared__ int ws[32];
    if (lane == 31) ws[wid] = x;
    __syncthreads();
    if (wid == 0) {
        int y = ws[lane];
#pragma unroll
        for (int o = 1; o < 32; o <<= 1) {
            int t = __shfl_up_sync(0xffffffffu, y, o);
            if (lane >= o) y += t;
        }
        ws[lane] = y;
    }
    __syncthreads();
    int incl = x + (wid ? ws[wid - 1] : 0);
    if (i < n) g_scan[i] = incl;
    if (threadIdx.x == 1023) g_bsum[blockIdx.x] = incl;
}

__global__ void scan2_kernel(int nb) {   // <<<1, 64>>>; nb <= 64
    int tid = threadIdx.x;
    int lane = tid & 31, wid = tid >> 5;
    int v = (tid < nb) ? g_bsum[tid] : 0;
    int x = v;
#pragma unroll
    for (int o = 1; o < 32; o <<= 1) {
        int t = __shfl_up_sync(0xffffffffu, x, o);
        if (lane >= o) x += t;
    }
    __shared__ int w0;
    if (wid == 0 && lane == 31) w0 = x;
    __syncthreads();
    if (wid == 1) x += w0;
    if (tid < nb) g_bsum[tid] = x;
}

__global__ void scan3_kernel(int n, int nb) {
    int i = blockIdx.x * blockDim.x + threadIdx.x;
    if (i > n) return;
    if (i == n) {
        g_rowstart[n] = g_bsum[nb - 1];
        return;
    }
    int blk = i >> 10;
    int excl = g_scan[i] - g_deg[i] + (blk ? g_bsum[blk - 1] : 0);
    g_rowstart[i] = excl;
    g_cursor[i]   = excl;
}

__global__ void scatter_kernel(int E) {
    int i = blockIdx.x * blockDim.x + threadIdx.x;
    if (i >= E) return;
    int d = g_dst[i];
    int pos = atomicAdd(&g_cursor[d], 1);
    g_csr[pos] = g_src[i];
}

// ---------------------------------------------------------------------------
// Tiled fp32 GEMM: C[n,m] = sum_k A[n,k] * B[k,m]
// BM=128, BN=128, BK=16, 256 threads, 8x8 per thread (4+4 split tiles).
// ---------------------------------------------------------------------------
__global__ __launch_bounds__(256)
void gemm_kernel(const float* __restrict__ A, const float* __restrict__ B,
                 float* __restrict__ C, int nRows, int K, int M) {
    __shared__ float As[16][136];
    __shared__ float Bs[16][128];

    int tid = threadIdx.x;
    int tx = tid & 15, ty = tid >> 4;
    int row0 = blockIdx.y * 128, col0 = blockIdx.x * 128;

    float acc[8][8];
#pragma unroll
    for (int i = 0; i < 8; i++)
#pragma unroll
        for (int j = 0; j < 8; j++) acc[i][j] = 0.f;

    for (int k0 = 0; k0 < K; k0 += 16) {
#pragma unroll
        for (int t = 0; t < 2; t++) {
            int f = tid + t * 256;
            int ar = f >> 2;
            int ac = (f & 3) << 2;
            int grow = row0 + ar;
            float4 v = make_float4(0.f, 0.f, 0.f, 0.f);
            if (grow < nRows)
                v = *(const float4*)(A + (size_t)grow * K + k0 + ac);
            As[ac + 0][ar] = v.x; As[ac + 1][ar] = v.y;
            As[ac + 2][ar] = v.z; As[ac + 3][ar] = v.w;
        }
#pragma unroll
        for (int t = 0; t < 2; t++) {
            int f = tid + t * 256;
            int br = f >> 5;
            int bc = (f & 31) << 2;
            *(float4*)&Bs[br][bc] =
                *(const float4*)(B + (size_t)(k0 + br) * M + col0 + bc);
        }
        __syncthreads();
#pragma unroll
        for (int k = 0; k < 16; k++) {
            float4 a0 = *(const float4*)&As[k][ty << 2];
            float4 a1 = *(const float4*)&As[k][64 + (ty << 2)];
            float4 b0 = *(const float4*)&Bs[k][tx << 2];
            float4 b1 = *(const float4*)&Bs[k][64 + (tx << 2)];
            float a[8] = {a0.x, a0.y, a0.z, a0.w, a1.x, a1.y, a1.z, a1.w};
            float b[8] = {b0.x, b0.y, b0.z, b0.w, b1.x, b1.y, b1.z, b1.w};
#pragma unroll
            for (int i = 0; i < 8; i++)
#pragma unroll
                for (int j = 0; j < 8; j++)
                    acc[i][j] += a[i] * b[j];
        }
        __syncthreads();
    }
#pragma unroll
    for (int i = 0; i < 8; i++) {
        int row = row0 + ((i < 4) ? ((ty << 2) + i) : (64 + (ty << 2) + i - 4));
        if (row >= nRows) continue;
        float* cp = C + (size_t)row * M + col0;
        *(float4*)(cp + (tx << 2)) =
            make_float4(acc[i][0], acc[i][1], acc[i][2], acc[i][3]);
        *(float4*)(cp + 64 + (tx << 2)) =
            make_float4(acc[i][4], acc[i][5], acc[i][6], acc[i][7]);
    }
}

// ---------------------------------------------------------------------------
// as_[n,h] = sum_c h[n,h,c]*a_src[h,c]; ad_ likewise. One warp per (n,h).
// ---------------------------------------------------------------------------
__global__ __launch_bounds__(256)
void attn_coef_kernel(const float* __restrict__ feat,
                      const float* __restrict__ a_src, const float* __restrict__ a_dst,
                      float* __restrict__ as_, float* __restrict__ ad_,
                      int n, int C) {
    int w = (blockIdx.x * blockDim.x + threadIdx.x) >> 5;
    int lane = threadIdx.x & 31;
    if (w >= n * 4) return;
    int node = w >> 2, h = w & 3;
    const float* fp = feat + (size_t)node * 4 * C + h * C;
    float s1 = 0.f, s2 = 0.f;
    for (int c = lane; c < C; c += 32) {
        float v = fp[c];
        s1 += v * a_src[h * C + c];
        s2 += v * a_dst[h * C + c];
    }
#pragma unroll
    for (int o = 16; o; o >>= 1) {
        s1 += __shfl_xor_sync(0xffffffffu, s1, o);
        s2 += __shfl_xor_sync(0xffffffffu, s2, o);
    }
    if (lane == 0) { as_[w] = s1; ad_[w] = s2; }
}

// ---------------------------------------------------------------------------
// Fused per-destination edge kernel (warp per dst node), atomic-free.
//   Loop A: ex = exp(leakyrelu(as[src]+ad[dst])) -> g_ex (CSR order), denom
//           (inv denominators also stored to g_inv for alpha_kernel)
//   Loop C: agg = inv * sum ex*feat[src] in registers
//   Epilogue in registers:
//     MODE 0: bias+ELU+LN+skip  -> xout   (layer 1, M=128)
//     MODE 1: bias+ELU+LN       -> xout   (layer 2, M=128)
//     MODE 2: mean-over-heads+b -> out    (layer 3, M=256)
// ---------------------------------------------------------------------------
template <int C, int MODE>
__global__ __launch_bounds__(256)
void gat_edge_kernel(const float* __restrict__ feat,
                     const float* __restrict__ as_,
                     const float* __restrict__ ad_,
                     float* __restrict__ inv_out,
                     float* __restrict__ xout,
                     const float* __restrict__ bias,
                     const float* __restrict__ lnw,
                     const float* __restrict__ lnb,
                     const float* __restrict__ skip,
                     const float* __restrict__ bskip,
                     int n) {
    constexpr int M  = 4 * C;
    constexpr int NR = M / 128;
    int w = (blockIdx.x * blockDim.x + threadIdx.x) >> 5;
    int lane = threadIdx.x & 31;
    if (w >= n) return;
    int start = g_rowstart[w];
    int end   = g_rowstart[w + 1];

    float4 adv = *(const float4*)(ad_ + 4 * (size_t)w);

    // ---- Loop A: ex + denominator partials ----
    float d0 = 0.f, d1 = 0.f, d2 = 0.f, d3 = 0.f;
    for (int i = start + lane; i < end; i += 32) {
        int sidx = g_csr[i];
        float4 av = *(const float4*)(as_ + 4 * (size_t)sidx);
        float e0 = av.x + adv.x; e0 = (e0 > 0.f) ? e0 : 0.2f * e0;
        float e1 = av.y + adv.y; e1 = (e1 > 0.f) ? e1 : 0.2f * e1;
        float e2 = av.z + adv.z; e2 = (e2 > 0.f) ? e2 : 0.2f * e2;
        float e3 = av.w + adv.w; e3 = (e3 > 0.f) ? e3 : 0.2f * e3;
        float x0 = __expf(e0), x1 = __expf(e1), x2 = __expf(e2), x3 = __expf(e3);
        *(float4*)(g_ex + (size_t)i * 4) = make_float4(x0, x1, x2, x3);
        d0 += x0; d1 += x1; d2 += x2; d3 += x3;
    }
    __syncwarp();
#pragma unroll
    for (int o = 16; o; o >>= 1) {
        d0 += __shfl_xor_sync(0xffffffffu, d0, o);
        d1 += __shfl_xor_sync(0xffffffffu, d1, o);
        d2 += __shfl_xor_sync(0xffffffffu, d2, o);
        d3 += __shfl_xor_sync(0xffffffffu, d3, o);
    }
    float i0 = 1.f / (d0 + 1e-16f);
    float i1 = 1.f / (d1 + 1e-16f);
    float i2 = 1.f / (d2 + 1e-16f);
    float i3 = 1.f / (d3 + 1e-16f);
    if (lane == 0)
        *(float4*)(inv_out + 4 * (size_t)w) = make_float4(i0, i1, i2, i3);

    // ---- Loop C: register-accumulated aggregation ----
    float4 acc[NR];
#pragma unroll
    for (int r = 0; r < NR; r++) acc[r] = make_float4(0.f, 0.f, 0.f, 0.f);

#pragma unroll 2
    for (int i = start; i < end; i++) {
        int sidx = g_csr[i];                                   // broadcast
        float4 ex = *(const float4*)(g_ex + (size_t)i * 4);    // broadcast
        const float4* fp = (const float4*)(feat + (size_t)sidx * M);
#pragma unroll
        for (int r = 0; r < NR; r++) {
            int f4 = r * 32 + lane;
            int h  = (f4 * 4) / C;
            float wgt = (h < 2) ? (h == 0 ? ex.x : ex.y)
                                : (h == 2 ? ex.z : ex.w);
            float4 v = fp[f4];
            acc[r].x += wgt * v.x; acc[r].y += wgt * v.y;
            acc[r].z += wgt * v.z; acc[r].w += wgt * v.w;
        }
    }

    // ---- scale by inv ----
#pragma unroll
    for (int r = 0; r < NR; r++) {
        int f4 = r * 32 + lane;
        int h  = (f4 * 4) / C;
        float inv = (h < 2) ? (h == 0 ? i0 : i1)
                            : (h == 2 ? i2 : i3);
        acc[r].x *= inv; acc[r].y *= inv; acc[r].z *= inv; acc[r].w *= inv;
    }

    if (MODE == 2) {
        // mean over 4 heads: feature f = r*128 + lane*4 + j, head = f/64.
        // acc0+acc1 merges {h0,h2} (lanes 0-15) / {h1,h3} (lanes 16-31);
        // shfl_xor(16) merges the rest. Lanes 0-15 hold out channels 4*lane..+3.
        float4 t;
        t.x = acc[0].x + acc[1].x;
        t.y = acc[0].y + acc[1].y;
        t.z = acc[0].z + acc[1].z;
        t.w = acc[0].w + acc[1].w;
        t.x += __shfl_xor_sync(0xffffffffu, t.x, 16);
        t.y += __shfl_xor_sync(0xffffffffu, t.y, 16);
        t.z += __shfl_xor_sync(0xffffffffu, t.z, 16);
        t.w += __shfl_xor_sync(0xffffffffu, t.w, 16);
        if (lane < 16) {
            float4 bb = *(const float4*)(bias + (lane << 2));
            float4 y = make_float4(0.25f * t.x + bb.x, 0.25f * t.y + bb.y,
                                   0.25f * t.z + bb.z, 0.25f * t.w + bb.w);
            *(float4*)(xout + (size_t)w * 64 + (lane << 2)) = y;
        }
    } else {
        // bias + ELU + LayerNorm(128) [+ skip + bskip]
        int f = lane << 2;
        float4 v = acc[0];
        float4 bb = *(const float4*)(bias + f);
        v.x += bb.x; v.y += bb.y; v.z += bb.z; v.w += bb.w;
        v.x = (v.x > 0.f) ? v.x : expm1f(v.x);
        v.y = (v.y > 0.f) ? v.y : expm1f(v.y);
        v.z = (v.z > 0.f) ? v.z : expm1f(v.z);
        v.w = (v.w > 0.f) ? v.w : expm1f(v.w);
        float s1 = v.x + v.y + v.z + v.w;
        float s2 = v.x * v.x + v.y * v.y + v.z * v.z + v.w * v.w;
#pragma unroll
        for (int o = 16; o; o >>= 1) {
            s1 += __shfl_xor_sync(0xffffffffu, s1, o);
            s2 += __shfl_xor_sync(0xffffffffu, s2, o);
        }
        float mu = s1 * (1.f / 128.f);
        float var = s2 * (1.f / 128.f) - mu * mu;
        float rinv = rsqrtf(var + 1e-5f);
        float4 wv = *(const float4*)(lnw + f);
        float4 bv = *(const float4*)(lnb + f);
        float4 y;
        y.x = (v.x - mu) * rinv * wv.x + bv.x;
        y.y = (v.y - mu) * rinv * wv.y + bv.y;
        y.z = (v.z - mu) * rinv * wv.z + bv.z;
        y.w = (v.w - mu) * rinv * wv.w + bv.w;
        if (MODE == 0) {
            float4 sk = *(const float4*)(skip + (size_t)w * 128 + f);
            float4 bs = *(const float4*)(bskip + f);
            y.x += sk.x + bs.x; y.y += sk.y + bs.y;
            y.z += sk.z + bs.z; y.w += sk.w + bs.w;
        }
        *(float4*)(xout + (size_t)w * 128 + f) = y;
    }
}

// ---------------------------------------------------------------------------
// Coalesced alpha output: alpha[e,h] = exp(leakyrelu(as[src]+ad[dst])) * inv[dst,h]
// (exp recomputed on identical inputs -> bit-identical to gat_edge's value)
// ---------------------------------------------------------------------------
__global__ __launch_bounds__(256)
void alpha_kernel(const float* __restrict__ as_,
                  const float* __restrict__ ad_,
                  const float* __restrict__ inv_,
                  float* __restrict__ alpha, int E) {
    int i = blockIdx.x * blockDim.x + threadIdx.x;
    if (i >= E) return;
    int s = g_src[i], d = g_dst[i];
    float4 av  = *(const float4*)(as_ + 4 * (size_t)s);
    float4 adv = *(const float4*)(ad_ + 4 * (size_t)d);
    float4 iv  = *(const float4*)(inv_ + 4 * (size_t)d);
    float e0 = av.x + adv.x; e0 = (e0 > 0.f) ? e0 : 0.2f * e0;
    float e1 = av.y + adv.y; e1 = (e1 > 0.f) ? e1 : 0.2f * e1;
    float e2 = av.z + adv.z; e2 = (e2 > 0.f) ? e2 : 0.2f * e2;
    float e3 = av.w + adv.w; e3 = (e3 > 0.f) ? e3 : 0.2f * e3;
    float4 y = make_float4(__expf(e0) * iv.x, __expf(e1) * iv.y,
                           __expf(e2) * iv.z, __expf(e3) * iv.w);
    *(float4*)(alpha + (size_t)i * 4) = y;
}

// ---------------------------------------------------------------------------
// Host
// ---------------------------------------------------------------------------
extern "C" void kernel_launch(void* const* d_in, const int* in_sizes, int n_in,
                              void* d_out, int out_size) {
    const float* x      = (const float*)d_in[0];
    const void*  ei     = d_in[1];
    const float* W1     = (const float*)d_in[2];
    const float* a_src1 = (const float*)d_in[3];
    const float* a_dst1 = (const float*)d_in[4];
    const float* b1     = (const float*)d_in[5];
    const float* ln1_w  = (const float*)d_in[6];
    const float* ln1_b  = (const float*)d_in[7];
    const float* Wskip  = (const float*)d_in[8];
    const float* bskip  = (const float*)d_in[9];
    const float* W2     = (const float*)d_in[10];
    const float* a_src2 = (const float*)d_in[11];
    const float* a_dst2 = (const float*)d_in[12];
    const float* b2     = (const float*)d_in[13];
    const float* ln2_w  = (const float*)d_in[14];
    const float* ln2_b  = (const float*)d_in[15];
    const float* W3     = (const float*)d_in[16];
    const float* a_src3 = (const float*)d_in[17];
    const float* a_dst3 = (const float*)d_in[18];
    const float* b3     = (const float*)d_in[19];

    int N = in_sizes[0] / 128;
    int E = in_sizes[1] / 2;

    float* out    = (float*)d_out;
    float* alpha1 = out + (size_t)N * 64;
    float* alpha2 = alpha1 + (size_t)E * 4;
    float* alpha3 = alpha2 + (size_t)E * 4;

    float *feat, *skip, *xin, *as_, *ad_, *inv_;
    cudaGetSymbolAddress((void**)&feat, g_feat);
    cudaGetSymbolAddress((void**)&skip, g_skip);
    cudaGetSymbolAddress((void**)&xin,  g_xin);
    cudaGetSymbolAddress((void**)&as_,  g_as);
    cudaGetSymbolAddress((void**)&ad_,  g_ad);
    cudaGetSymbolAddress((void**)&inv_, g_inv);

    const int TB = 256;
    dim3 gemm_grid1(1, (N + 127) / 128);
    dim3 gemm_grid2(2, (N + 127) / 128);
    int attn_blocks = (N * 4 * 32 + TB - 1) / TB;
    int edgeE_blocks = (E + TB - 1) / TB;
    int node_warp_blocks = (N * 32 + TB - 1) / TB;
    int zero_blocks = (N + TB - 1) / TB;
    int nb = (N + 1023) / 1024;

    // ---- CSR build (once; shared by all 3 layers) ----
    detect_idx_kernel<<<1, 32>>>((const long long*)ei, N);
    zero_deg_kernel<<<zero_blocks, TB>>>(N);
    convert_idx_kernel<<<edgeE_blocks, TB>>>(ei, E);
    scan1_kernel<<<nb, 1024>>>(N);
    scan2_kernel<<<1, 64>>>(nb);
    scan3_kernel<<<(N + 1 + TB - 1) / TB, TB>>>(N, nb);
    scatter_kernel<<<edgeE_blocks, TB>>>(E);

    // ---- Layer 1 ----
    gemm_kernel<<<gemm_grid1, TB>>>(x, W1, feat, N, 128, 128);
    gemm_kernel<<<gemm_grid1, TB>>>(x, Wskip, skip, N, 128, 128);
    attn_coef_kernel<<<attn_blocks, TB>>>(feat, a_src1, a_dst1, as_, ad_, N, 32);
    gat_edge_kernel<32, 0><<<node_warp_blocks, TB>>>(
        feat, as_, ad_, inv_, xin, b1, ln1_w, ln1_b, skip, bskip, N);
    alpha_kernel<<<edgeE_blocks, TB>>>(as_, ad_, inv_, alpha1, E);

    // ---- Layer 2 ----
    gemm_kernel<<<gemm_grid1, TB>>>(xin, W2, feat, N, 128, 128);
    attn_coef_kernel<<<attn_blocks, TB>>>(feat, a_src2, a_dst2, as_, ad_, N, 32);
    gat_edge_kernel<32, 1><<<node_warp_blocks, TB>>>(
        feat, as_, ad_, inv_, xin, b2, ln2_w, ln2_b, nullptr, nullptr, N);
    alpha_kernel<<<edgeE_blocks, TB>>>(as_, ad_, inv_, alpha2, E);

    // ---- Layer 3 ----
    gemm_kernel<<<gemm_grid2, TB>>>(xin, W3, feat, N, 128, 256);
    attn_coef_kernel<<<attn_blocks, TB>>>(feat, a_src3, a_dst3, as_, ad_, N, 64);
    gat_edge_kernel<64, 2><<<node_warp_blocks, TB>>>(
        feat, as_, ad_, inv_, out, b3, nullptr, nullptr, nullptr, nullptr, N);
    alpha_kernel<<<edgeE_blocks, TB>>>(as_, ad_, inv_, alpha3, E);
}